// round 1
// baseline (speedup 1.0000x reference)
#include <cuda_runtime.h>
#include <math.h>

#define B     8
#define T     2048
#define DM    64
#define NH    6
#define HS    10
#define DFF   256
#define BT    (B*T)        // 16384
#define BH    (B*NH)       // 48
#define QTILE 128
#define NQT   (T/QTILE)    // 16

// ---------------- scratch (device globals; no allocation allowed) ----------
__device__ float g_q[BH * T * HS];
__device__ float g_k[BH * T * HS];
__device__ float g_v[BH * T * HS];
__device__ float g_attn[BT * (NH*HS)];   // [B,T,60]
__device__ float g_x1[BT * DM];          // after first residual+LN

// ================= Kernel 1: per-head fused QKV projection =================
// qkv[b,h,t,e] = sum_d x[b,t,d] * W_qkv[h,d,e];  e<10->Q, 10..19->K, 20..29->V
__global__ __launch_bounds__(256) void k_qkv(const float* __restrict__ x,
                                             const float* __restrict__ Wqkv) {
    __shared__ float Wsm[NH * DM * 30];   // 11520 floats = 46KB
    __shared__ float xrow[DM];
    const int tid = threadIdx.x;
    for (int i = tid; i < NH*DM*30; i += 256) Wsm[i] = Wqkv[i];
    __syncthreads();

    const int row0 = blockIdx.x * 128;
    for (int r = 0; r < 128; ++r) {
        const int rg = row0 + r;           // global row in [0,BT)
        if (tid < DM) xrow[tid] = x[rg * DM + tid];
        __syncthreads();
        if (tid < NH*30) {
            const int h = tid / 30, e = tid % 30;
            const float* w = &Wsm[h*DM*30 + e];
            float acc = 0.f;
            #pragma unroll
            for (int d = 0; d < DM; ++d) acc = fmaf(xrow[d], w[d*30], acc);
            const int b = rg / T, t = rg % T;
            const int base = ((b*NH + h) * T + t) * HS;
            if (e < 10)       g_q[base + e]        = acc;
            else if (e < 20)  g_k[base + (e-10)]   = acc;
            else              g_v[base + (e-20)]   = acc;
        }
        __syncthreads();
    }
}

// ================= Kernel 2: causal flash attention ========================
// grid: (NQT, BH); block: 128 threads, thread = one q row of the tile.
__global__ __launch_bounds__(128) void k_attn() {
    __shared__ float ksm[QTILE][12];
    __shared__ float vsm[QTILE][12];
    const int tid = threadIdx.x;
    const int qt  = blockIdx.x;
    const int bh  = blockIdx.y;
    const int qg  = qt * QTILE + tid;

    const float scale = rsqrtf((float)HS);
    float q[10];
    {
        const int base = (bh * T + qg) * HS;
        #pragma unroll
        for (int d = 0; d < 10; ++d) q[d] = g_q[base + d] * scale;
    }
    float acc[10];
    #pragma unroll
    for (int d = 0; d < 10; ++d) acc[d] = 0.f;
    float ssum = 0.f;

    for (int c = 0; c <= qt; ++c) {
        const int src = (bh * T + c * QTILE + tid) * HS;
        #pragma unroll
        for (int d = 0; d < 5; ++d) {
            float2 kk = *(const float2*)&g_k[src + 2*d];
            float2 vv = *(const float2*)&g_v[src + 2*d];
            ksm[tid][2*d] = kk.x;  ksm[tid][2*d+1] = kk.y;
            vsm[tid][2*d] = vv.x;  vsm[tid][2*d+1] = vv.y;
        }
        ksm[tid][10] = ksm[tid][11] = 0.f;
        vsm[tid][10] = vsm[tid][11] = 0.f;
        __syncthreads();

        const int smax = (c == qt) ? (tid + 1) : QTILE;
        #pragma unroll 4
        for (int s = 0; s < smax; ++s) {
            const float4 k0 = *(const float4*)&ksm[s][0];
            const float4 k1 = *(const float4*)&ksm[s][4];
            const float2 k2 = *(const float2*)&ksm[s][8];
            float dot = q[0]*k0.x + q[1]*k0.y + q[2]*k0.z + q[3]*k0.w
                      + q[4]*k1.x + q[5]*k1.y + q[6]*k1.z + q[7]*k1.w
                      + q[8]*k2.x + q[9]*k2.y;
            const float p = __expf(dot);
            ssum += p;
            const float4 v0 = *(const float4*)&vsm[s][0];
            const float4 v1 = *(const float4*)&vsm[s][4];
            const float2 v2 = *(const float2*)&vsm[s][8];
            acc[0] = fmaf(p, v0.x, acc[0]); acc[1] = fmaf(p, v0.y, acc[1]);
            acc[2] = fmaf(p, v0.z, acc[2]); acc[3] = fmaf(p, v0.w, acc[3]);
            acc[4] = fmaf(p, v1.x, acc[4]); acc[5] = fmaf(p, v1.y, acc[5]);
            acc[6] = fmaf(p, v1.z, acc[6]); acc[7] = fmaf(p, v1.w, acc[7]);
            acc[8] = fmaf(p, v2.x, acc[8]); acc[9] = fmaf(p, v2.y, acc[9]);
        }
        __syncthreads();
    }

    const float inv = 1.f / ssum;
    const int b = bh / NH, h = bh % NH;
    float* out = &g_attn[(b * T + qg) * (NH*HS) + h * HS];
    #pragma unroll
    for (int d = 0; d < 10; ++d) out[d] = acc[d] * inv;
}

// ========= Kernel 3: out-proj + bias, post-LN on branch, residual ==========
// 4 rows per block; 64 threads per row.
__global__ __launch_bounds__(256) void k_proj_ln(const float* __restrict__ x,
                                                 const float* __restrict__ Wp,
                                                 const float* __restrict__ bp,
                                                 const float* __restrict__ g1,
                                                 const float* __restrict__ b1ln) {
    __shared__ float a_sm[4][60];
    __shared__ float sa[4][64];
    __shared__ float mu[4], ri[4];
    const int tid = threadIdx.x;
    const int y = tid >> 6, j = tid & 63;
    const int row = blockIdx.x * 4 + y;

    if (j < 60) a_sm[y][j] = g_attn[row * 60 + j];
    __syncthreads();

    float acc = bp[j];
    #pragma unroll
    for (int i = 0; i < 60; ++i) acc = fmaf(a_sm[y][i], Wp[i*64 + j], acc);
    sa[y][j] = acc;
    __syncthreads();

    if (j == 0) {
        float m = 0.f;
        #pragma unroll
        for (int i = 0; i < 64; ++i) m += sa[y][i];
        m *= (1.f/64.f);
        float v = 0.f;
        #pragma unroll
        for (int i = 0; i < 64; ++i) { float d = sa[y][i] - m; v = fmaf(d, d, v); }
        mu[y] = m;
        ri[y] = rsqrtf(v * (1.f/64.f) + 1e-5f);
    }
    __syncthreads();

    const float val = x[row*64 + j] + (sa[y][j] - mu[y]) * ri[y] * g1[j] + b1ln[j];
    g_x1[row*64 + j] = val;
}

// ========= Kernel 4: FFN (gelu exact) + bias, post-LN, residual -> out =====
// 16 rows per block; 256 threads.
__global__ __launch_bounds__(256) void k_ffn(const float* __restrict__ W1,
                                             const float* __restrict__ bb1,
                                             const float* __restrict__ W2,
                                             const float* __restrict__ bb2,
                                             const float* __restrict__ g2,
                                             const float* __restrict__ b2ln,
                                             float* __restrict__ out) {
    __shared__ float xs[16][64];     // 4KB
    __shared__ float hs[16][256];    // 16KB
    __shared__ float part[4][16][64];// 16KB
    __shared__ float ffn[16][64];    // 4KB
    __shared__ float mu[16], ri[16];
    const int tid = threadIdx.x;
    const int row0 = blockIdx.x * 16;

    // load 16 x1 rows: 16*64 = 1024 floats
    for (int i = tid; i < 16*64; i += 256) xs[i>>6][i&63] = g_x1[row0*64 + i];
    __syncthreads();

    // h = gelu(x1 @ W1 + b1) : thread tid owns hidden column tid for all 16 rows
    {
        float hacc[16];
        const float bb = bb1[tid];
        #pragma unroll
        for (int r = 0; r < 16; ++r) hacc[r] = bb;
        for (int d = 0; d < 64; ++d) {
            const float w = W1[d*256 + tid];
            #pragma unroll
            for (int r = 0; r < 16; ++r) hacc[r] = fmaf(xs[r][d], w, hacc[r]);
        }
        #pragma unroll
        for (int r = 0; r < 16; ++r) {
            const float v = hacc[r];
            hs[r][tid] = 0.5f * v * (1.f + erff(v * 0.70710678118654752f));
        }
    }
    __syncthreads();

    // ffn = h @ W2 : threads split i-range into 4 groups of 64
    {
        const int j = tid & 63, g = tid >> 6;
        float acc[16];
        #pragma unroll
        for (int r = 0; r < 16; ++r) acc[r] = 0.f;
        for (int i = g*64; i < g*64 + 64; ++i) {
            const float w = W2[i*64 + j];
            #pragma unroll
            for (int r = 0; r < 16; ++r) acc[r] = fmaf(hs[r][i], w, acc[r]);
        }
        #pragma unroll
        for (int r = 0; r < 16; ++r) part[g][r][j] = acc[r];
    }
    __syncthreads();

    {
        const int j = tid & 63, g = tid >> 6;
        const float bb = bb2[j];
        #pragma unroll
        for (int rr = 0; rr < 4; ++rr) {
            const int r = g*4 + rr;
            ffn[r][j] = part[0][r][j] + part[1][r][j] + part[2][r][j] + part[3][r][j] + bb;
        }
    }
    __syncthreads();

    if (tid < 16) {
        float m = 0.f;
        #pragma unroll
        for (int i = 0; i < 64; ++i) m += ffn[tid][i];
        m *= (1.f/64.f);
        float v = 0.f;
        #pragma unroll
        for (int i = 0; i < 64; ++i) { float d = ffn[tid][i] - m; v = fmaf(d, d, v); }
        mu[tid] = m;
        ri[tid] = rsqrtf(v * (1.f/64.f) + 1e-5f);
    }
    __syncthreads();

    {
        const int j = tid & 63, g = tid >> 6;
        #pragma unroll
        for (int rr = 0; rr < 4; ++rr) {
            const int r = g*4 + rr;
            out[(row0 + r)*64 + j] =
                xs[r][j] + (ffn[r][j] - mu[r]) * ri[r] * g2[j] + b2ln[j];
        }
    }
}

// ===========================================================================
extern "C" void kernel_launch(void* const* d_in, const int* in_sizes, int n_in,
                              void* d_out, int out_size) {
    const float* x     = (const float*)d_in[0];
    const float* Wqkv  = (const float*)d_in[1];
    const float* Wproj = (const float*)d_in[2];
    const float* bproj = (const float*)d_in[3];
    const float* ln1g  = (const float*)d_in[4];
    const float* ln1b  = (const float*)d_in[5];
    const float* W1    = (const float*)d_in[6];
    const float* b1    = (const float*)d_in[7];
    const float* W2    = (const float*)d_in[8];
    const float* b2    = (const float*)d_in[9];
    const float* ln2g  = (const float*)d_in[10];
    const float* ln2b  = (const float*)d_in[11];
    float* out = (float*)d_out;

    k_qkv<<<BT/128, 256>>>(x, Wqkv);
    dim3 ag(NQT, BH);
    k_attn<<<ag, 128>>>();
    k_proj_ln<<<BT/4, 256>>>(x, Wproj, bproj, ln1g, ln1b);
    k_ffn<<<BT/16, 256>>>(W1, b1, W2, b2, ln2g, ln2b, out);
}

// round 2
// speedup vs baseline: 1.0039x; 1.0039x over previous
#include <cuda_runtime.h>
#include <math.h>

#define B     8
#define T     2048
#define DM    64
#define NH    6
#define HS    10
#define BT    (B*T)        // 16384
#define BH    (B*NH)       // 48
#define QT2   256
#define NQT2  (T/QT2)      // 8

typedef unsigned long long u64;

// ---------------- packed f32x2 helpers ----------------
__device__ __forceinline__ u64 f2_mul(u64 a, u64 b) {
    u64 d; asm("mul.rn.f32x2 %0,%1,%2;" : "=l"(d) : "l"(a), "l"(b)); return d;
}
__device__ __forceinline__ u64 f2_fma(u64 a, u64 b, u64 c) {
    u64 d; asm("fma.rn.f32x2 %0,%1,%2,%3;" : "=l"(d) : "l"(a), "l"(b), "l"(c)); return d;
}
__device__ __forceinline__ u64 f2_add(u64 a, u64 b) {
    u64 d; asm("add.rn.f32x2 %0,%1,%2;" : "=l"(d) : "l"(a), "l"(b)); return d;
}
__device__ __forceinline__ u64 pk(float lo, float hi) {
    u64 r; asm("mov.b64 %0,{%1,%2};" : "=l"(r) : "f"(lo), "f"(hi)); return r;
}
__device__ __forceinline__ void upk(float& lo, float& hi, u64 a) {
    asm("mov.b64 {%0,%1},%2;" : "=f"(lo), "=f"(hi) : "l"(a));
}

// ---------------- scratch ----------------
__device__ __align__(16) float g_q[BH * T * 12];
__device__ __align__(16) float g_k[BH * T * 12];
__device__ __align__(16) float g_v[BH * T * 12];
__device__ __align__(16) float g_attn[BT * 60];

// ================= Kernel 1: QKV projection =================
// 128 rows/block, 256 threads: 2 threads per row, each computes 15 of 30 outs/head.
__global__ __launch_bounds__(256) void k_qkv(const float* __restrict__ x,
                                             const float* __restrict__ Wqkv) {
    __shared__ __align__(16) float Wsm[180 * 64];   // e-major: [(h*30+e)][d], 46KB
    const int tid  = threadIdx.x;
    const int r    = tid & 127;
    const int half = tid >> 7;
    const int row  = blockIdx.x * 128 + r;

    // transpose W: src idx = ((h*64+d)*30+e)
    for (int idx = tid; idx < NH*DM*30; idx += 256) {
        int h = idx / (DM*30); int rem = idx % (DM*30);
        int d = rem / 30;      int e   = rem % 30;
        Wsm[(h*30 + e)*64 + d] = Wqkv[idx];
    }
    __syncthreads();

    // x row into packed registers
    u64 xp[32];
    {
        const ulonglong2* gx = (const ulonglong2*)(x + row * 64);
        #pragma unroll
        for (int i = 0; i < 16; ++i) { ulonglong2 u = gx[i]; xp[2*i] = u.x; xp[2*i+1] = u.y; }
    }

    const int b = row >> 11, t = row & 2047;
    const int ebase = half * 15;

    for (int h = 0; h < NH; ++h) {
        float f[15];
        #pragma unroll
        for (int e = 0; e < 15; ++e) {
            const ulonglong2* w2 = (const ulonglong2*)&Wsm[(h*30 + ebase + e)*64];
            u64 c0, c1, c2, c3;
            {
                ulonglong2 wa = w2[0], wb = w2[1];
                c0 = f2_mul(xp[0], wa.x); c1 = f2_mul(xp[1], wa.y);
                c2 = f2_mul(xp[2], wb.x); c3 = f2_mul(xp[3], wb.y);
            }
            #pragma unroll
            for (int g = 1; g < 8; ++g) {
                ulonglong2 wa = w2[2*g], wb = w2[2*g+1];
                c0 = f2_fma(xp[4*g+0], wa.x, c0);
                c1 = f2_fma(xp[4*g+1], wa.y, c1);
                c2 = f2_fma(xp[4*g+2], wb.x, c2);
                c3 = f2_fma(xp[4*g+3], wb.y, c3);
            }
            c0 = f2_add(c0, c1); c2 = f2_add(c2, c3); c0 = f2_add(c0, c2);
            float l, hh; upk(l, hh, c0);
            f[e] = l + hh;
        }
        const int off = ((b*NH + h)*T + t) * 12;
        if (half == 0) {
            // f[0..9]=q, f[10..14]=k[0..4]
            float4* oq = (float4*)&g_q[off];
            oq[0] = make_float4(f[0], f[1], f[2], f[3]);
            oq[1] = make_float4(f[4], f[5], f[6], f[7]);
            oq[2] = make_float4(f[8], f[9], 0.f, 0.f);
            float4* ok = (float4*)&g_k[off];
            ok[0] = make_float4(f[10], f[11], f[12], f[13]);
            g_k[off + 4] = f[14];
        } else {
            // f[0..4]=k[5..9], f[5..14]=v
            g_k[off + 5] = f[0]; g_k[off + 6] = f[1]; g_k[off + 7] = f[2];
            *(float4*)&g_k[off + 8] = make_float4(f[3], f[4], 0.f, 0.f);
            float4* ov = (float4*)&g_v[off];
            ov[0] = make_float4(f[5], f[6], f[7], f[8]);
            ov[1] = make_float4(f[9], f[10], f[11], f[12]);
            ov[2] = make_float4(f[13], f[14], 0.f, 0.f);
        }
    }
}

// ================= Kernel 2: causal flash attention =================
// grid (8, 48), 128 threads; each thread owns rows tid and tid+128 of a 256-row tile.
__constant__ int QT_PERM[8] = {3, 2, 1, 0, 4, 5, 6, 7};

#define ATT_Q(qv, av, sv)                                                     \
    {   u64 m0 = f2_mul(qv[0], kA.x); u64 m1 = f2_mul(qv[1], kA.y);           \
        u64 m2 = f2_mul(qv[2], kB.x);                                         \
        m0 = f2_fma(qv[3], kB.y, m0); m1 = f2_fma(qv[4], kC.x, m1);           \
        m2 = f2_fma(qv[5], kC.y, m2);                                         \
        m0 = f2_add(m0, m1); m0 = f2_add(m0, m2);                             \
        float dl, dh; upk(dl, dh, m0);                                        \
        float p = __expf(dl + dh); sv += p; u64 pp = pk(p, p);                \
        av[0] = f2_fma(pp, vA.x, av[0]); av[1] = f2_fma(pp, vA.y, av[1]);     \
        av[2] = f2_fma(pp, vB.x, av[2]); av[3] = f2_fma(pp, vB.y, av[3]);     \
        av[4] = f2_fma(pp, vC.x, av[4]); av[5] = f2_fma(pp, vC.y, av[5]); }

__global__ __launch_bounds__(128) void k_attn() {
    __shared__ __align__(16) float ksm[QT2 * 12];
    __shared__ __align__(16) float vsm[QT2 * 12];
    const int tid = threadIdx.x;
    const int qt  = QT_PERM[blockIdx.x];
    const int bh  = blockIdx.y;
    const int q0  = qt*QT2 + tid;
    const int q1  = q0 + 128;

    const float sc = rsqrtf((float)HS);
    u64 qa[6], qb[6];
    {
        const float4* g0 = (const float4*)&g_q[(bh*T + q0)*12];
        const float4* g1 = (const float4*)&g_q[(bh*T + q1)*12];
        #pragma unroll
        for (int i = 0; i < 3; ++i) {
            float4 a = g0[i], bv = g1[i];
            qa[2*i]   = pk(a.x*sc, a.y*sc); qa[2*i+1] = pk(a.z*sc, a.w*sc);
            qb[2*i]   = pk(bv.x*sc, bv.y*sc); qb[2*i+1] = pk(bv.z*sc, bv.w*sc);
        }
    }
    u64 acc0[6], acc1[6];
    #pragma unroll
    for (int i = 0; i < 6; ++i) { acc0[i] = 0ull; acc1[i] = 0ull; }
    float ss0 = 0.f, ss1 = 0.f;

    for (int c = 0; c <= qt; ++c) {
        {
            const float4* gk0 = (const float4*)&g_k[(bh*T + c*QT2 + tid)*12];
            const float4* gv0 = (const float4*)&g_v[(bh*T + c*QT2 + tid)*12];
            float4* dk0 = (float4*)&ksm[tid*12];
            float4* dv0 = (float4*)&vsm[tid*12];
            dk0[0]=gk0[0]; dk0[1]=gk0[1]; dk0[2]=gk0[2];
            dv0[0]=gv0[0]; dv0[1]=gv0[1]; dv0[2]=gv0[2];
            const float4* gk1 = (const float4*)&g_k[(bh*T + c*QT2 + 128 + tid)*12];
            const float4* gv1 = (const float4*)&g_v[(bh*T + c*QT2 + 128 + tid)*12];
            float4* dk1 = (float4*)&ksm[(tid+128)*12];
            float4* dv1 = (float4*)&vsm[(tid+128)*12];
            dk1[0]=gk1[0]; dk1[1]=gk1[1]; dk1[2]=gk1[2];
            dv1[0]=gv1[0]; dv1[1]=gv1[1]; dv1[2]=gv1[2];
        }
        __syncthreads();

        if (c < qt) {
            #pragma unroll 2
            for (int s = 0; s < QT2; ++s) {
                const ulonglong2* kr = (const ulonglong2*)&ksm[s*12];
                const ulonglong2* vr = (const ulonglong2*)&vsm[s*12];
                ulonglong2 kA = kr[0], kB = kr[1], kC = kr[2];
                ulonglong2 vA = vr[0], vB = vr[1], vC = vr[2];
                ATT_Q(qa, acc0, ss0)
                ATT_Q(qb, acc1, ss1)
            }
        } else {
            for (int s = 0; s <= tid; ++s) {
                const ulonglong2* kr = (const ulonglong2*)&ksm[s*12];
                const ulonglong2* vr = (const ulonglong2*)&vsm[s*12];
                ulonglong2 kA = kr[0], kB = kr[1], kC = kr[2];
                ulonglong2 vA = vr[0], vB = vr[1], vC = vr[2];
                ATT_Q(qa, acc0, ss0)
                ATT_Q(qb, acc1, ss1)
            }
            #pragma unroll 2
            for (int s = tid+1; s <= tid+128; ++s) {
                const ulonglong2* kr = (const ulonglong2*)&ksm[s*12];
                const ulonglong2* vr = (const ulonglong2*)&vsm[s*12];
                ulonglong2 kA = kr[0], kB = kr[1], kC = kr[2];
                ulonglong2 vA = vr[0], vB = vr[1], vC = vr[2];
                ATT_Q(qb, acc1, ss1)
            }
        }
        __syncthreads();
    }

    const int b = bh / NH, h = bh % NH;
    {
        const float inv = 1.f / ss0;
        float o[12];
        #pragma unroll
        for (int i = 0; i < 5; ++i) upk(o[2*i], o[2*i+1], acc0[i]);
        float2* p = (float2*)&g_attn[(b*T + q0)*60 + h*10];
        #pragma unroll
        for (int i = 0; i < 5; ++i) p[i] = make_float2(o[2*i]*inv, o[2*i+1]*inv);
    }
    {
        const float inv = 1.f / ss1;
        float o[12];
        #pragma unroll
        for (int i = 0; i < 5; ++i) upk(o[2*i], o[2*i+1], acc1[i]);
        float2* p = (float2*)&g_attn[(b*T + q1)*60 + h*10];
        #pragma unroll
        for (int i = 0; i < 5; ++i) p[i] = make_float2(o[2*i]*inv, o[2*i+1]*inv);
    }
}

// ================= Kernel 3: fused proj + LN1 + FFN + LN2 =================
// 32 rows/block, 256 threads.  smem: attn[32*60] | xs[32*64] | hs[32*260]
#define HSP 260
__global__ __launch_bounds__(256) void k_tail(const float* __restrict__ x,
                                              const float* __restrict__ Wp,
                                              const float* __restrict__ bp,
                                              const float* __restrict__ g1,
                                              const float* __restrict__ b1ln,
                                              const float* __restrict__ W1,
                                              const float* __restrict__ bb1,
                                              const float* __restrict__ W2,
                                              const float* __restrict__ bb2,
                                              const float* __restrict__ g2,
                                              const float* __restrict__ b2ln,
                                              float* __restrict__ out) {
    extern __shared__ __align__(16) float sm[];
    float* atn = sm;                 // 32*60
    float* xs  = sm + 32*60;         // 32*64
    float* hs  = sm + 32*60 + 32*64; // 32*260

    const int tid  = threadIdx.x;
    const int row0 = blockIdx.x * 32;

    for (int idx = tid; idx < 32*60; idx += 256) atn[idx] = g_attn[row0*60 + idx];
    __syncthreads();

    // ---- proj + LN1 -> xs ----
    {
        const int r  = tid >> 3;
        const int cg = tid & 7;
        const int c0 = cg * 8;
        u64 pa0 = 0, pa1 = 0, pa2 = 0, pa3 = 0;
        #pragma unroll 4
        for (int i = 0; i < 60; ++i) {
            float a = atn[r*60 + i];
            u64 ap = pk(a, a);
            const ulonglong2* w2 = (const ulonglong2*)&Wp[i*64 + c0];
            ulonglong2 wA = w2[0], wB = w2[1];
            pa0 = f2_fma(ap, wA.x, pa0); pa1 = f2_fma(ap, wA.y, pa1);
            pa2 = f2_fma(ap, wB.x, pa2); pa3 = f2_fma(ap, wB.y, pa3);
        }
        {
            const ulonglong2* bb = (const ulonglong2*)&bp[c0];
            ulonglong2 bA = bb[0], bB = bb[1];
            pa0 = f2_add(pa0, bA.x); pa1 = f2_add(pa1, bA.y);
            pa2 = f2_add(pa2, bB.x); pa3 = f2_add(pa3, bB.y);
        }
        float sa[8];
        upk(sa[0], sa[1], pa0); upk(sa[2], sa[3], pa1);
        upk(sa[4], sa[5], pa2); upk(sa[6], sa[7], pa3);
        float s = 0.f, q = 0.f;
        #pragma unroll
        for (int i = 0; i < 8; ++i) { s += sa[i]; q = fmaf(sa[i], sa[i], q); }
        #pragma unroll
        for (int m = 4; m; m >>= 1) {
            s += __shfl_xor_sync(0xffffffffu, s, m);
            q += __shfl_xor_sync(0xffffffffu, q, m);
        }
        const float mu = s * (1.f/64.f);
        const float ri = rsqrtf(q * (1.f/64.f) - mu*mu + 1e-5f);
        const float4* xr = (const float4*)(x + (row0 + r)*64 + c0);
        const float4* gg = (const float4*)(g1 + c0);
        const float4* bb = (const float4*)(b1ln + c0);
        float4 xA = xr[0], xB = xr[1], gA = gg[0], gB = gg[1], bA = bb[0], bB = bb[1];
        float4 o0, o1;
        o0.x = xA.x + (sa[0]-mu)*ri*gA.x + bA.x;  o0.y = xA.y + (sa[1]-mu)*ri*gA.y + bA.y;
        o0.z = xA.z + (sa[2]-mu)*ri*gA.z + bA.z;  o0.w = xA.w + (sa[3]-mu)*ri*gA.w + bA.w;
        o1.x = xB.x + (sa[4]-mu)*ri*gB.x + bB.x;  o1.y = xB.y + (sa[5]-mu)*ri*gB.y + bB.y;
        o1.z = xB.z + (sa[6]-mu)*ri*gB.z + bB.z;  o1.w = xB.w + (sa[7]-mu)*ri*gB.w + bB.w;
        *(float4*)&xs[r*64 + c0]     = o0;
        *(float4*)&xs[r*64 + c0 + 4] = o1;
    }
    __syncthreads();

    const int w  = tid >> 5;
    const int co = tid & 31;
    const int rb = w * 4;

    // ---- gemm1: hs = gelu(xs @ W1 + b1) ----
    {
        const int c0 = co * 8;
        u64 ac[4][4];
        #pragma unroll
        for (int r = 0; r < 4; ++r)
            #pragma unroll
            for (int j = 0; j < 4; ++j) ac[r][j] = 0ull;

        for (int d = 0; d < 64; d += 4) {
            float4 xv[4];
            #pragma unroll
            for (int r = 0; r < 4; ++r) xv[r] = *(const float4*)&xs[(rb+r)*64 + d];
            #pragma unroll
            for (int dd = 0; dd < 4; ++dd) {
                const ulonglong2* w1p = (const ulonglong2*)&W1[(d+dd)*256 + c0];
                ulonglong2 wA = w1p[0], wB = w1p[1];
                #pragma unroll
                for (int r = 0; r < 4; ++r) {
                    float xvv = ((const float*)&xv[r])[dd];
                    u64 px = pk(xvv, xvv);
                    ac[r][0] = f2_fma(px, wA.x, ac[r][0]);
                    ac[r][1] = f2_fma(px, wA.y, ac[r][1]);
                    ac[r][2] = f2_fma(px, wB.x, ac[r][2]);
                    ac[r][3] = f2_fma(px, wB.y, ac[r][3]);
                }
            }
        }
        const ulonglong2* bbp = (const ulonglong2*)&bb1[c0];
        ulonglong2 bA = bbp[0], bB = bbp[1];
        #pragma unroll
        for (int r = 0; r < 4; ++r) {
            ac[r][0] = f2_add(ac[r][0], bA.x); ac[r][1] = f2_add(ac[r][1], bA.y);
            ac[r][2] = f2_add(ac[r][2], bB.x); ac[r][3] = f2_add(ac[r][3], bB.y);
            float h[8];
            upk(h[0], h[1], ac[r][0]); upk(h[2], h[3], ac[r][1]);
            upk(h[4], h[5], ac[r][2]); upk(h[6], h[7], ac[r][3]);
            #pragma unroll
            for (int j = 0; j < 8; ++j)
                h[j] = 0.5f * h[j] * (1.f + erff(h[j] * 0.70710678118654752f));
            *(float4*)&hs[(rb+r)*HSP + c0]     = make_float4(h[0], h[1], h[2], h[3]);
            *(float4*)&hs[(rb+r)*HSP + c0 + 4] = make_float4(h[4], h[5], h[6], h[7]);
        }
    }
    __syncthreads();

    // ---- gemm2: ffn = hs @ W2 + b2; LN2; out = xs + LN2(ffn) ----
    {
        const int c = 2 * co;
        u64 bacc[4];
        #pragma unroll
        for (int r = 0; r < 4; ++r) bacc[r] = 0ull;

        for (int i = 0; i < 256; i += 4) {
            float4 hv[4];
            #pragma unroll
            for (int r = 0; r < 4; ++r) hv[r] = *(const float4*)&hs[(rb+r)*HSP + i];
            #pragma unroll
            for (int ii = 0; ii < 4; ++ii) {
                u64 wv = *(const u64*)&W2[(i+ii)*64 + c];
                #pragma unroll
                for (int r = 0; r < 4; ++r) {
                    float hvv = ((const float*)&hv[r])[ii];
                    u64 ph = pk(hvv, hvv);
                    bacc[r] = f2_fma(ph, wv, bacc[r]);
                }
            }
        }
        u64 b2v = *(const u64*)&bb2[c];
        float fv[4][2];
        #pragma unroll
        for (int r = 0; r < 4; ++r) {
            bacc[r] = f2_add(bacc[r], b2v);
            upk(fv[r][0], fv[r][1], bacc[r]);
        }
        float mu[4], ri[4];
        #pragma unroll
        for (int r = 0; r < 4; ++r) {
            float s = fv[r][0] + fv[r][1];
            float q = fmaf(fv[r][0], fv[r][0], fv[r][1]*fv[r][1]);
            #pragma unroll
            for (int m = 16; m; m >>= 1) {
                s += __shfl_xor_sync(0xffffffffu, s, m);
                q += __shfl_xor_sync(0xffffffffu, q, m);
            }
            mu[r] = s * (1.f/64.f);
            ri[r] = rsqrtf(q * (1.f/64.f) - mu[r]*mu[r] + 1e-5f);
        }
        float2 g2v = *(const float2*)&g2[c];
        float2 b2l = *(const float2*)&b2ln[c];
        #pragma unroll
        for (int r = 0; r < 4; ++r) {
            float2 xv = *(const float2*)&xs[(rb+r)*64 + c];
            float2 o;
            o.x = xv.x + (fv[r][0]-mu[r])*ri[r]*g2v.x + b2l.x;
            o.y = xv.y + (fv[r][1]-mu[r])*ri[r]*g2v.y + b2l.y;
            *(float2*)&out[(row0 + rb + r)*64 + c] = o;
        }
    }
}

// ===========================================================================
extern "C" void kernel_launch(void* const* d_in, const int* in_sizes, int n_in,
                              void* d_out, int out_size) {
    const float* x     = (const float*)d_in[0];
    const float* Wqkv  = (const float*)d_in[1];
    const float* Wproj = (const float*)d_in[2];
    const float* bproj = (const float*)d_in[3];
    const float* ln1g  = (const float*)d_in[4];
    const float* ln1b  = (const float*)d_in[5];
    const float* W1    = (const float*)d_in[6];
    const float* b1    = (const float*)d_in[7];
    const float* W2    = (const float*)d_in[8];
    const float* b2    = (const float*)d_in[9];
    const float* ln2g  = (const float*)d_in[10];
    const float* ln2b  = (const float*)d_in[11];
    float* out = (float*)d_out;

    k_qkv<<<BT/128, 256>>>(x, Wqkv);
    dim3 ag(NQT2, BH);
    k_attn<<<ag, 128>>>();
    const int smemTail = (32*60 + 32*64 + 32*HSP) * (int)sizeof(float);  // 48KB
    k_tail<<<BT/32, 256, smemTail>>>(x, Wproj, bproj, ln1g, ln1b,
                                     W1, b1, W2, b2, ln2g, ln2b, out);
}

// round 5
// speedup vs baseline: 1.5366x; 1.5306x over previous
#include <cuda_runtime.h>
#include <math.h>

#define B     8
#define T     2048
#define DM    64
#define NH    6
#define HS    10
#define BT    (B*T)        // 16384
#define BH    (B*NH)       // 48

typedef unsigned long long u64;

// ---------------- packed f32x2 helpers ----------------
__device__ __forceinline__ u64 f2_mul(u64 a, u64 b) {
    u64 d; asm("mul.rn.f32x2 %0,%1,%2;" : "=l"(d) : "l"(a), "l"(b)); return d;
}
__device__ __forceinline__ u64 f2_fma(u64 a, u64 b, u64 c) {
    u64 d; asm("fma.rn.f32x2 %0,%1,%2,%3;" : "=l"(d) : "l"(a), "l"(b), "l"(c)); return d;
}
__device__ __forceinline__ u64 f2_add(u64 a, u64 b) {
    u64 d; asm("add.rn.f32x2 %0,%1,%2;" : "=l"(d) : "l"(a), "l"(b)); return d;
}
__device__ __forceinline__ u64 pk(float lo, float hi) {
    u64 r; asm("mov.b64 %0,{%1,%2};" : "=l"(r) : "f"(lo), "f"(hi)); return r;
}
__device__ __forceinline__ void upk(float& lo, float& hi, u64 a) {
    asm("mov.b64 {%0,%1},%2;" : "=f"(lo), "=f"(hi) : "l"(a));
}
__device__ __forceinline__ float ex2f(float x) {
    float r; asm("ex2.approx.f32 %0,%1;" : "=f"(r) : "f"(x)); return r;
}

// ---------------- scratch ----------------
__device__ __align__(16) float g_q [BH * T * 12];
__device__ __align__(16) float g_kp[BH * (T/2) * 20];   // [bh][t/2][d=0..9][2]
__device__ __align__(16) float g_vp[BH * (T/2) * 20];
__device__ __align__(16) float g_attn[BT * 60];

// ================= Kernel 1: QKV projection =================
// 128 rows/block, 256 threads: 2 threads per row, each computes 15 of 30 outs/head.
__global__ __launch_bounds__(256) void k_qkv(const float* __restrict__ x,
                                             const float* __restrict__ Wqkv) {
    __shared__ __align__(16) float Wsm[180 * 64];   // e-major: [(h*30+e)][d]
    const int tid  = threadIdx.x;
    const int r    = tid & 127;
    const int half = tid >> 7;
    const int row  = blockIdx.x * 128 + r;

    for (int idx = tid; idx < NH*DM*30; idx += 256) {
        int h = idx / (DM*30); int rem = idx % (DM*30);
        int d = rem / 30;      int e   = rem % 30;
        Wsm[(h*30 + e)*64 + d] = Wqkv[idx];
    }
    __syncthreads();

    u64 xp[32];
    {
        const ulonglong2* gx = (const ulonglong2*)(x + row * 64);
        #pragma unroll
        for (int i = 0; i < 16; ++i) { ulonglong2 u = gx[i]; xp[2*i] = u.x; xp[2*i+1] = u.y; }
    }

    const int b = row >> 11, t = row & 2047;
    const int tp = t >> 1, par = t & 1;
    const int ebase = half * 15;

    for (int h = 0; h < NH; ++h) {
        float f[15];
        #pragma unroll
        for (int e = 0; e < 15; ++e) {
            const ulonglong2* w2 = (const ulonglong2*)&Wsm[(h*30 + ebase + e)*64];
            u64 c0, c1, c2, c3;
            {
                ulonglong2 wa = w2[0], wb = w2[1];
                c0 = f2_mul(xp[0], wa.x); c1 = f2_mul(xp[1], wa.y);
                c2 = f2_mul(xp[2], wb.x); c3 = f2_mul(xp[3], wb.y);
            }
            #pragma unroll
            for (int g = 1; g < 8; ++g) {
                ulonglong2 wa = w2[2*g], wb = w2[2*g+1];
                c0 = f2_fma(xp[4*g+0], wa.x, c0);
                c1 = f2_fma(xp[4*g+1], wa.y, c1);
                c2 = f2_fma(xp[4*g+2], wb.x, c2);
                c3 = f2_fma(xp[4*g+3], wb.y, c3);
            }
            c0 = f2_add(c0, c1); c2 = f2_add(c2, c3); c0 = f2_add(c0, c2);
            float l, hh; upk(l, hh, c0);
            f[e] = l + hh;
        }
        const int bh   = b*NH + h;
        const int kvbs = (bh*(T/2) + tp) * 20;
        if (half == 0) {
            const int off = (bh*T + t) * 12;
            float4* oq = (float4*)&g_q[off];
            oq[0] = make_float4(f[0], f[1], f[2], f[3]);
            oq[1] = make_float4(f[4], f[5], f[6], f[7]);
            oq[2] = make_float4(f[8], f[9], 0.f, 0.f);
            #pragma unroll
            for (int d = 0; d < 5; ++d) g_kp[kvbs + 2*d + par] = f[10 + d];
        } else {
            #pragma unroll
            for (int d = 0; d < 5; ++d) g_kp[kvbs + 2*(5+d) + par] = f[d];
            #pragma unroll
            for (int d = 0; d < 10; ++d) g_vp[kvbs + 2*d + par] = f[5 + d];
        }
    }
}

// ================= Kernel 2: causal flash attention, s-packed =================
// 1D grid of 384 blocks: bid -> (qt descending for LPT, bh). 256 threads = 256 q rows.
// K/V chunks of 128 s (64 pairs), double-buffered.
#define ATT_BODY(PHI)                                                          \
    {   const ulonglong2* kp2 = (const ulonglong2*)(ksP + sp*20);              \
        const ulonglong2* vp2 = (const ulonglong2*)(vsP + sp*20);              \
        ulonglong2 kA=kp2[0], kB=kp2[1], kC=kp2[2], kD=kp2[3], kE=kp2[4];      \
        u64 s0 = f2_mul(qp[0], kA.x), s1 = f2_mul(qp[1], kA.y);                \
        s0 = f2_fma(qp[2], kB.x, s0); s1 = f2_fma(qp[3], kB.y, s1);            \
        s0 = f2_fma(qp[4], kC.x, s0); s1 = f2_fma(qp[5], kC.y, s1);            \
        s0 = f2_fma(qp[6], kD.x, s0); s1 = f2_fma(qp[7], kD.y, s1);            \
        s0 = f2_fma(qp[8], kE.x, s0); s1 = f2_fma(qp[9], kE.y, s1);            \
        s0 = f2_add(s0, s1);                                                   \
        float dl, dh; upk(dl, dh, s0);                                         \
        float pl = ex2f(dl);                                                   \
        float ph = PHI;                                                        \
        u64 pp = pk(pl, ph);                                                   \
        ssp = f2_add(ssp, pp);                                                 \
        ulonglong2 vA=vp2[0], vB=vp2[1], vC=vp2[2], vD=vp2[3], vE=vp2[4];      \
        acc[0]=f2_fma(pp,vA.x,acc[0]); acc[1]=f2_fma(pp,vA.y,acc[1]);          \
        acc[2]=f2_fma(pp,vB.x,acc[2]); acc[3]=f2_fma(pp,vB.y,acc[3]);          \
        acc[4]=f2_fma(pp,vC.x,acc[4]); acc[5]=f2_fma(pp,vC.y,acc[5]);          \
        acc[6]=f2_fma(pp,vD.x,acc[6]); acc[7]=f2_fma(pp,vD.y,acc[7]);          \
        acc[8]=f2_fma(pp,vE.x,acc[8]); acc[9]=f2_fma(pp,vE.y,acc[9]); }

__global__ __launch_bounds__(256, 2) void k_attn() {
    __shared__ __align__(16) float ksm[2][1280];
    __shared__ __align__(16) float vsm[2][1280];
    const int tid = threadIdx.x;
    const int bx  = 7 - (int)(blockIdx.x / 48);   // heavy tiles first (LPT)
    const int bh  = blockIdx.x % 48;
    const int q   = bx * 256 + tid;

    u64 qp[10];
    {
        const float4* gq = (const float4*)&g_q[(bh*T + q)*12];
        float4 a = gq[0], b4 = gq[1], c4 = gq[2];
        const float SC = 0.31622776601683794f * 1.4426950408889634f; // rsqrt(10)*log2e
        qp[0]=pk(a.x*SC,a.x*SC);  qp[1]=pk(a.y*SC,a.y*SC);
        qp[2]=pk(a.z*SC,a.z*SC);  qp[3]=pk(a.w*SC,a.w*SC);
        qp[4]=pk(b4.x*SC,b4.x*SC); qp[5]=pk(b4.y*SC,b4.y*SC);
        qp[6]=pk(b4.z*SC,b4.z*SC); qp[7]=pk(b4.w*SC,b4.w*SC);
        qp[8]=pk(c4.x*SC,c4.x*SC); qp[9]=pk(c4.y*SC,c4.y*SC);
    }
    u64 acc[10];
    #pragma unroll
    for (int i = 0; i < 10; ++i) acc[i] = 0ull;
    u64 ssp = 0ull;

    const int nc = 2*bx + 2;
    const float4* srcK0 = (const float4*)&g_kp[(size_t)(bh*(T/2)) * 20];
    const float4* srcV0 = (const float4*)&g_vp[(size_t)(bh*(T/2)) * 20];

    // prologue: chunk 0 -> buffer 0   (chunk = 64 pairs * 5 float4 = 320 f4 each of K,V)
    for (int i = tid; i < 640; i += 256) {
        float4 v = (i < 320) ? srcK0[i] : srcV0[i - 320];
        if (i < 320) ((float4*)ksm[0])[i] = v; else ((float4*)vsm[0])[i - 320] = v;
    }
    __syncthreads();

    for (int c = 0; c < nc; ++c) {
        const int cb = c & 1;
        float4 st0, st1, st2;
        const bool more = (c + 1 < nc);
        if (more) {
            const float4* sK = srcK0 + (c+1)*320;
            const float4* sV = srcV0 + (c+1)*320;
            st0 = (tid < 320) ? sK[tid] : sV[tid - 320];
            { int i = tid + 256; st1 = (i < 320) ? sK[i] : sV[i - 320]; }
            if (tid < 128) st2 = sV[tid + 192];     // i = tid+512 -> V idx tid+192
        }

        const float* ksP = ksm[cb];
        const float* vsP = vsm[cb];
        const int rel = q - (c << 7);
        int nf = (rel + 1) >> 1;
        nf = nf < 0 ? 0 : (nf > 64 ? 64 : nf);
        #pragma unroll 2
        for (int sp = 0; sp < nf; ++sp) ATT_BODY(ex2f(dh))
        if ((unsigned)rel < 128u && !(rel & 1)) {
            const int sp = rel >> 1;
            ATT_BODY(0.f)
        }

        if (more) {
            float4* dK = (float4*)ksm[cb ^ 1];
            float4* dV = (float4*)vsm[cb ^ 1];
            if (tid < 320) dK[tid] = st0; else dV[tid - 320] = st0;
            { int i = tid + 256; if (i < 320) dK[i] = st1; else dV[i - 320] = st1; }
            if (tid < 128) dV[tid + 192] = st2;
        }
        __syncthreads();
    }

    float sl, sh; upk(sl, sh, ssp);
    const float inv = 1.f / (sl + sh);
    float* o = &g_attn[((bh/NH)*T + q)*60 + (bh%NH)*10];
    #pragma unroll
    for (int d = 0; d < 10; d += 2) {
        float l0, h0, l1, h1;
        upk(l0, h0, acc[d]); upk(l1, h1, acc[d+1]);
        *(float2*)&o[d] = make_float2((l0 + h0)*inv, (l1 + h1)*inv);
    }
}

// ================= Kernel 3: fused proj + LN1 + FFN + LN2 =================
#define HSP 260
__global__ __launch_bounds__(256) void k_tail(const float* __restrict__ x,
                                              const float* __restrict__ Wp,
                                              const float* __restrict__ bp,
                                              const float* __restrict__ g1,
                                              const float* __restrict__ b1ln,
                                              const float* __restrict__ W1,
                                              const float* __restrict__ bb1,
                                              const float* __restrict__ W2,
                                              const float* __restrict__ bb2,
                                              const float* __restrict__ g2,
                                              const float* __restrict__ b2ln,
                                              float* __restrict__ out) {
    extern __shared__ __align__(16) float sm[];
    float* atn = sm;                 // 32*60
    float* xs  = sm + 32*60;         // 32*64
    float* hs  = sm + 32*60 + 32*64; // 32*260

    const int tid  = threadIdx.x;
    const int row0 = blockIdx.x * 32;

    for (int idx = tid; idx < 32*60; idx += 256) atn[idx] = g_attn[row0*60 + idx];
    __syncthreads();

    {
        const int r  = tid >> 3;
        const int cg = tid & 7;
        const int c0 = cg * 8;
        u64 pa0 = 0, pa1 = 0, pa2 = 0, pa3 = 0;
        #pragma unroll 4
        for (int i = 0; i < 60; ++i) {
            float a = atn[r*60 + i];
            u64 ap = pk(a, a);
            const ulonglong2* w2 = (const ulonglong2*)&Wp[i*64 + c0];
            ulonglong2 wA = w2[0], wB = w2[1];
            pa0 = f2_fma(ap, wA.x, pa0); pa1 = f2_fma(ap, wA.y, pa1);
            pa2 = f2_fma(ap, wB.x, pa2); pa3 = f2_fma(ap, wB.y, pa3);
        }
        {
            const ulonglong2* bb = (const ulonglong2*)&bp[c0];
            ulonglong2 bA = bb[0], bB = bb[1];
            pa0 = f2_add(pa0, bA.x); pa1 = f2_add(pa1, bA.y);
            pa2 = f2_add(pa2, bB.x); pa3 = f2_add(pa3, bB.y);
        }
        float sa[8];
        upk(sa[0], sa[1], pa0); upk(sa[2], sa[3], pa1);
        upk(sa[4], sa[5], pa2); upk(sa[6], sa[7], pa3);
        float s = 0.f, qq = 0.f;
        #pragma unroll
        for (int i = 0; i < 8; ++i) { s += sa[i]; qq = fmaf(sa[i], sa[i], qq); }
        #pragma unroll
        for (int m = 4; m; m >>= 1) {
            s  += __shfl_xor_sync(0xffffffffu, s, m);
            qq += __shfl_xor_sync(0xffffffffu, qq, m);
        }
        const float mu = s * (1.f/64.f);
        const float ri = rsqrtf(qq * (1.f/64.f) - mu*mu + 1e-5f);
        const float4* xr = (const float4*)(x + (row0 + r)*64 + c0);
        const float4* gg = (const float4*)(g1 + c0);
        const float4* bb = (const float4*)(b1ln + c0);
        float4 xA = xr[0], xB = xr[1], gA = gg[0], gB = gg[1], bA = bb[0], bB = bb[1];
        float4 o0, o1;
        o0.x = xA.x + (sa[0]-mu)*ri*gA.x + bA.x;  o0.y = xA.y + (sa[1]-mu)*ri*gA.y + bA.y;
        o0.z = xA.z + (sa[2]-mu)*ri*gA.z + bA.z;  o0.w = xA.w + (sa[3]-mu)*ri*gA.w + bA.w;
        o1.x = xB.x + (sa[4]-mu)*ri*gB.x + bB.x;  o1.y = xB.y + (sa[5]-mu)*ri*gB.y + bB.y;
        o1.z = xB.z + (sa[6]-mu)*ri*gB.z + bB.z;  o1.w = xB.w + (sa[7]-mu)*ri*gB.w + bB.w;
        *(float4*)&xs[r*64 + c0]     = o0;
        *(float4*)&xs[r*64 + c0 + 4] = o1;
    }
    __syncthreads();

    const int w  = tid >> 5;
    const int co = tid & 31;
    const int rb = w * 4;

    {
        const int c0 = co * 8;
        u64 ac[4][4];
        #pragma unroll
        for (int r = 0; r < 4; ++r)
            #pragma unroll
            for (int j = 0; j < 4; ++j) ac[r][j] = 0ull;

        for (int d = 0; d < 64; d += 4) {
            float4 xv[4];
            #pragma unroll
            for (int r = 0; r < 4; ++r) xv[r] = *(const float4*)&xs[(rb+r)*64 + d];
            #pragma unroll
            for (int dd = 0; dd < 4; ++dd) {
                const ulonglong2* w1p = (const ulonglong2*)&W1[(d+dd)*256 + c0];
                ulonglong2 wA = w1p[0], wB = w1p[1];
                #pragma unroll
                for (int r = 0; r < 4; ++r) {
                    float xvv = ((const float*)&xv[r])[dd];
                    u64 px = pk(xvv, xvv);
                    ac[r][0] = f2_fma(px, wA.x, ac[r][0]);
                    ac[r][1] = f2_fma(px, wA.y, ac[r][1]);
                    ac[r][2] = f2_fma(px, wB.x, ac[r][2]);
                    ac[r][3] = f2_fma(px, wB.y, ac[r][3]);
                }
            }
        }
        const ulonglong2* bbp = (const ulonglong2*)&bb1[c0];
        ulonglong2 bA = bbp[0], bB = bbp[1];
        #pragma unroll
        for (int r = 0; r < 4; ++r) {
            ac[r][0] = f2_add(ac[r][0], bA.x); ac[r][1] = f2_add(ac[r][1], bA.y);
            ac[r][2] = f2_add(ac[r][2], bB.x); ac[r][3] = f2_add(ac[r][3], bB.y);
            float h[8];
            upk(h[0], h[1], ac[r][0]); upk(h[2], h[3], ac[r][1]);
            upk(h[4], h[5], ac[r][2]); upk(h[6], h[7], ac[r][3]);
            #pragma unroll
            for (int j = 0; j < 8; ++j)
                h[j] = 0.5f * h[j] * (1.f + erff(h[j] * 0.70710678118654752f));
            *(float4*)&hs[(rb+r)*HSP + c0]     = make_float4(h[0], h[1], h[2], h[3]);
            *(float4*)&hs[(rb+r)*HSP + c0 + 4] = make_float4(h[4], h[5], h[6], h[7]);
        }
    }
    __syncthreads();

    {
        const int c = 2 * co;
        u64 bacc[4];
        #pragma unroll
        for (int r = 0; r < 4; ++r) bacc[r] = 0ull;

        for (int i = 0; i < 256; i += 4) {
            float4 hv[4];
            #pragma unroll
            for (int r = 0; r < 4; ++r) hv[r] = *(const float4*)&hs[(rb+r)*HSP + i];
            #pragma unroll
            for (int ii = 0; ii < 4; ++ii) {
                u64 wv = *(const u64*)&W2[(i+ii)*64 + c];
                #pragma unroll
                for (int r = 0; r < 4; ++r) {
                    float hvv = ((const float*)&hv[r])[ii];
                    u64 ph = pk(hvv, hvv);
                    bacc[r] = f2_fma(ph, wv, bacc[r]);
                }
            }
        }
        u64 b2v = *(const u64*)&bb2[c];
        float fv[4][2];
        #pragma unroll
        for (int r = 0; r < 4; ++r) {
            bacc[r] = f2_add(bacc[r], b2v);
            upk(fv[r][0], fv[r][1], bacc[r]);
        }
        float mu[4], ri[4];
        #pragma unroll
        for (int r = 0; r < 4; ++r) {
            float s = fv[r][0] + fv[r][1];
            float qq = fmaf(fv[r][0], fv[r][0], fv[r][1]*fv[r][1]);
            #pragma unroll
            for (int m = 16; m; m >>= 1) {
                s  += __shfl_xor_sync(0xffffffffu, s, m);
                qq += __shfl_xor_sync(0xffffffffu, qq, m);
            }
            mu[r] = s * (1.f/64.f);
            ri[r] = rsqrtf(qq * (1.f/64.f) - mu[r]*mu[r] + 1e-5f);
        }
        float2 g2v = *(const float2*)&g2[c];
        float2 b2l = *(const float2*)&b2ln[c];
        #pragma unroll
        for (int r = 0; r < 4; ++r) {
            float2 xv = *(const float2*)&xs[(rb+r)*64 + c];
            float2 o;
            o.x = xv.x + (fv[r][0]-mu[r])*ri[r]*g2v.x + b2l.x;
            o.y = xv.y + (fv[r][1]-mu[r])*ri[r]*g2v.y + b2l.y;
            *(float2*)&out[(row0 + rb + r)*64 + c] = o;
        }
    }
}

// ===========================================================================
extern "C" void kernel_launch(void* const* d_in, const int* in_sizes, int n_in,
                              void* d_out, int out_size) {
    const float* x     = (const float*)d_in[0];
    const float* Wqkv  = (const float*)d_in[1];
    const float* Wproj = (const float*)d_in[2];
    const float* bproj = (const float*)d_in[3];
    const float* ln1g  = (const float*)d_in[4];
    const float* ln1b  = (const float*)d_in[5];
    const float* W1    = (const float*)d_in[6];
    const float* b1    = (const float*)d_in[7];
    const float* W2    = (const float*)d_in[8];
    const float* b2    = (const float*)d_in[9];
    const float* ln2g  = (const float*)d_in[10];
    const float* ln2b  = (const float*)d_in[11];
    float* out = (float*)d_out;

    k_qkv<<<BT/128, 256>>>(x, Wqkv);
    k_attn<<<8*48, 256>>>();
    const int smemTail = (32*60 + 32*64 + 32*HSP) * (int)sizeof(float);
    k_tail<<<BT/32, 256, smemTail>>>(x, Wproj, bproj, ln1g, ln1b,
                                     W1, b1, W2, b2, ln2g, ln2b, out);
}